// round 13
// baseline (speedup 1.0000x reference)
#include <cuda_runtime.h>
#include <cuda_bf16.h>
#include <cstdint>

typedef uint32_t u32;

#define S_LEN 2048
#define NH 16
#define DIM 64
#define BLKM 64          // T rows per CTA
#define BLKS 64          // K/V rows per j-step
#define NMB 32           // S_LEN / BLKM
#define ROWSTRIDE 3072   // 3*NH*DIM floats between consecutive s rows

#define HL 8192          // one [64][64] bf16 half-tile (hi or lo)
// smem layout (each buffer = hi tile then lo tile, off64 swizzled)
#define OFF_Q   0        // pass 1: 2Q split tiles; pass 2: K ping buffer
#define OFF_K   16384    // pass 1: K split tiles;  pass 2: K pong buffer
#define OFF_V   32768    // pass 1: fp32 K staging; pass 2: V split tiles
#define OFF_O2  49152
#define SMEM_TOTAL 65536               // -> 3 CTAs/SM
#define RED_OFF OFF_K                  // f32 staging for cross-warp reduce (16KB)

#define NTILE 528                      // sum_{mb} (mb+1)
// A1 tile cache: [bh][tri(mb)+j][4096 floats], fp32, written pass 1 / read pass 2
// by the SAME thread at the SAME addresses. ~277 MB, .cs streamed.
__device__ float g_s1[(size_t)32 * NTILE * 4096];
// Converted K tile cache: exact 16KB byte image of the split-bf16 swizzled K tile.
// Written during pass-1 convert, cp.async'd straight into smem in pass 2. ~277 MB.
__device__ uint4 g_kc[(size_t)32 * NTILE * 1024];

// ------------------------------------------------------------------ helpers
__device__ __forceinline__ u32 smem_u32(const void* p) {
    u32 a; asm("{ .reg .u64 t; cvta.to.shared.u64 t, %1; cvt.u32.u64 %0, t; }"
               : "=r"(a) : "l"(p));
    return a;
}
__device__ __forceinline__ u32 off64(int r, int cb) { return (u32)(r * 128 + (cb ^ ((r & 7) << 4))); }

__device__ __forceinline__ void ldsm4(u32 a, u32& r0, u32& r1, u32& r2, u32& r3) {
    asm volatile("ldmatrix.sync.aligned.m8n8.x4.shared.b16 {%0,%1,%2,%3}, [%4];"
        : "=r"(r0), "=r"(r1), "=r"(r2), "=r"(r3) : "r"(a));
}
__device__ __forceinline__ void ldsm4t(u32 a, u32& r0, u32& r1, u32& r2, u32& r3) {
    asm volatile("ldmatrix.sync.aligned.m8n8.x4.trans.shared.b16 {%0,%1,%2,%3}, [%4];"
        : "=r"(r0), "=r"(r1), "=r"(r2), "=r"(r3) : "r"(a));
}
__device__ __forceinline__ void mma_bf16(float* c, u32 a0, u32 a1, u32 a2, u32 a3,
                                         u32 b0, u32 b1) {
    asm volatile("mma.sync.aligned.m16n8k16.row.col.f32.bf16.bf16.f32 "
        "{%0,%1,%2,%3}, {%4,%5,%6,%7}, {%8,%9}, {%0,%1,%2,%3};"
        : "+f"(c[0]), "+f"(c[1]), "+f"(c[2]), "+f"(c[3])
        : "r"(a0), "r"(a1), "r"(a2), "r"(a3), "r"(b0), "r"(b1));
}
// fast truncation split: hi = top16 (PRMT pack), lo = x - hi (rn bf16x2 pack)
__device__ __forceinline__ void split_pack(float v0, float v1, u32& hp, u32& lp) {
    u32 u0 = __float_as_uint(v0), u1 = __float_as_uint(v1);
    asm("prmt.b32 %0, %1, %2, 0x7632;" : "=r"(hp) : "r"(u0), "r"(u1));
    float lo0 = v0 - __uint_as_float(u0 & 0xFFFF0000u);
    float lo1 = v1 - __uint_as_float(u1 & 0xFFFF0000u);
    asm("cvt.rn.satfinite.bf16x2.f32 %0, %1, %2;" : "=r"(lp) : "f"(lo1), "f"(lo0));
}
// streaming (evict-first) scratch access
__device__ __forceinline__ void stg_cs4(float* p, float a, float b, float c, float d) {
    asm volatile("st.global.cs.v4.f32 [%0], {%1,%2,%3,%4};"
        :: "l"(p), "f"(a), "f"(b), "f"(c), "f"(d) : "memory");
}
__device__ __forceinline__ void ldg_cs4(const float* p, float& a, float& b, float& c, float& d) {
    asm volatile("ld.global.cs.v4.f32 {%0,%1,%2,%3}, [%4];"
        : "=f"(a), "=f"(b), "=f"(c), "=f"(d) : "l"(p));
}
__device__ __forceinline__ void stg_cs2(char* p, u32 a, u32 b) {
    asm volatile("st.global.cs.v2.b32 [%0], {%1,%2};" :: "l"(p), "r"(a), "r"(b) : "memory");
}

#define CP_COMMIT() asm volatile("cp.async.commit_group;" ::: "memory")
#define CP_WAIT0()  asm volatile("cp.async.wait_group 0;" ::: "memory")

// ---- cp.async: 64x64 fp32 tile -> fp32 stage (128 thr, 8x16B each) ----
__device__ __forceinline__ void cpasync64(u32 stg, const float* src, int tid) {
#pragma unroll
    for (int it = 0; it < 8; ++it) {
        int f = tid + it * 128;
        int s = f >> 4, dq = (f & 15) << 2;
        u32 dst = stg + (u32)(s * 256 + dq * 4);
        const float* g = src + (size_t)s * ROWSTRIDE + dq;
        asm volatile("cp.async.cg.shared.global [%0], [%1], 16;" :: "r"(dst), "l"(g));
    }
    CP_COMMIT();
}
// ---- cp.async: 16KB linear gmem -> smem (prebuilt bf16 tile image) ----
__device__ __forceinline__ void cpasync_lin(u32 dst, const char* src, int tid) {
#pragma unroll
    for (int it = 0; it < 8; ++it) {
        int off = (tid + it * 128) * 16;
        asm volatile("cp.async.cg.shared.global [%0], [%1], 16;"
                     :: "r"(dst + (u32)off), "l"(src + off));
    }
    CP_COMMIT();
}

// ---- convert fp32 stage -> K split-bf16 tiles AND stream tile image to scratch ----
__device__ __forceinline__ void convert_stage_store(char* sm, int stageOff, char* kscr, int tid) {
#pragma unroll
    for (int it = 0; it < 8; ++it) {
        int f = tid + it * 128;
        int s = f >> 4, dq = (f & 15) << 2;
        float4 v = *reinterpret_cast<const float4*>(sm + stageOff + s * 256 + dq * 4);
        u32 hp0, lp0, hp1, lp1;
        split_pack(v.x, v.y, hp0, lp0);
        split_pack(v.z, v.w, hp1, lp1);
        u32 o = off64(s, dq << 1);
        *reinterpret_cast<uint2*>(sm + OFF_K + o)      = make_uint2(hp0, hp1);
        *reinterpret_cast<uint2*>(sm + OFF_K + HL + o) = make_uint2(lp0, lp1);
        stg_cs2(kscr + o,      hp0, hp1);
        stg_cs2(kscr + HL + o, lp0, lp1);
    }
}

// ---- direct LDG load: 64 x 64 fp32 -> split-bf16 hi/lo swizzled smem (128 thr) ----
__device__ __forceinline__ void load_split(char* sm, int base, const float* src,
                                           float scale, int tid) {
#pragma unroll
    for (int it = 0; it < 8; ++it) {
        int f = tid + it * 128;
        int s = f >> 4, dq = (f & 15) << 2;
        float4 v = *reinterpret_cast<const float4*>(src + (size_t)s * ROWSTRIDE + dq);
        u32 hp0, lp0, hp1, lp1;
        split_pack(v.x * scale, v.y * scale, hp0, lp0);
        split_pack(v.z * scale, v.w * scale, hp1, lp1);
        u32 o = off64(s, dq << 1);
        *reinterpret_cast<uint2*>(sm + base + o)      = make_uint2(hp0, hp1);
        *reinterpret_cast<uint2*>(sm + base + HL + o) = make_uint2(lp0, lp1);
    }
}

// ---- GEMM1: acc[32x32 slice] += A[64x64] * (B[64x64])^T, 3-term split ----
__device__ __forceinline__ void gemm_nT(u32 aHi, u32 bHi, float (&acc)[2][4][4],
                                        int lane, int mbase, int nbase) {
    const int arL = lane & 15, acL = (lane >> 4) << 4;
    const int brL = ((lane >> 4) << 3) + (lane & 7), bcL = ((lane >> 3) & 1) << 4;
#pragma unroll
    for (int kk = 0; kk < 4; ++kk) {
        const int kb = kk << 5;
        u32 aH[2][4], aL[2][4];
#pragma unroll
        for (int mt = 0; mt < 2; ++mt) {
            u32 ad = aHi + off64(mbase + mt * 16 + arL, kb + acL);
            ldsm4(ad,      aH[mt][0], aH[mt][1], aH[mt][2], aH[mt][3]);
            ldsm4(ad + HL, aL[mt][0], aL[mt][1], aL[mt][2], aL[mt][3]);
        }
#pragma unroll
        for (int nt2 = 0; nt2 < 2; ++nt2) {
            u32 bd = bHi + off64(nbase + nt2 * 16 + brL, kb + bcL);
            u32 bh0, bh1, bh2, bh3, bl0, bl1, bl2, bl3;
            ldsm4(bd,      bh0, bh1, bh2, bh3);
            ldsm4(bd + HL, bl0, bl1, bl2, bl3);
#pragma unroll
            for (int mt = 0; mt < 2; ++mt) {
                float* c0 = acc[mt][nt2 * 2];
                float* c1 = acc[mt][nt2 * 2 + 1];
                mma_bf16(c0, aH[mt][0], aH[mt][1], aH[mt][2], aH[mt][3], bh0, bh1);
                mma_bf16(c1, aH[mt][0], aH[mt][1], aH[mt][2], aH[mt][3], bh2, bh3);
                mma_bf16(c0, aH[mt][0], aH[mt][1], aH[mt][2], aH[mt][3], bl0, bl1);
                mma_bf16(c1, aH[mt][0], aH[mt][1], aH[mt][2], aH[mt][3], bl2, bl3);
                mma_bf16(c0, aL[mt][0], aL[mt][1], aL[mt][2], aL[mt][3], bh0, bh1);
                mma_bf16(c1, aL[mt][0], aL[mt][1], aL[mt][2], aL[mt][3], bh2, bh3);
            }
        }
    }
}

// ---- mask (absolute row/col) + in-register split into A-operand packs ----
__device__ __forceinline__ void mask_pack(float (&acc)[2][4][4],
                                          u32 (&pH)[2][2][4], u32 (&pL)[2][2][4],
                                          int lane, int rowAbs0, int colAbs0, bool diag) {
    if (diag) {
#pragma unroll
        for (int mt = 0; mt < 2; ++mt)
#pragma unroll
            for (int nt = 0; nt < 4; ++nt) {
                int col = colAbs0 + nt * 8 + ((lane & 3) << 1);
#pragma unroll
                for (int rr = 0; rr < 2; ++rr) {
                    int row = rowAbs0 + mt * 16 + (lane >> 2) + rr * 8;
                    if (col     > row) acc[mt][nt][rr * 2 + 0] = 0.0f;
                    if (col + 1 > row) acc[mt][nt][rr * 2 + 1] = 0.0f;
                }
            }
    }
#pragma unroll
    for (int mt = 0; mt < 2; ++mt)
#pragma unroll
        for (int kk = 0; kk < 2; ++kk) {
            split_pack(acc[mt][2*kk  ][0], acc[mt][2*kk  ][1], pH[mt][kk][0], pL[mt][kk][0]);
            split_pack(acc[mt][2*kk  ][2], acc[mt][2*kk  ][3], pH[mt][kk][1], pL[mt][kk][1]);
            split_pack(acc[mt][2*kk+1][0], acc[mt][2*kk+1][1], pH[mt][kk][2], pL[mt][kk][2]);
            split_pack(acc[mt][2*kk+1][2], acc[mt][2*kk+1][3], pH[mt][kk][3], pL[mt][kk][3]);
        }
}

// ---- GEMM2: po[32x64] += S_slice(regs, 32 k) * B[k-slice x 64], B via ldmatrix.trans ----
__device__ __forceinline__ void gemm2_reg(const u32 (&pH)[2][2][4], const u32 (&pL)[2][2][4],
                                          u32 bHi, float (&po)[2][8][4],
                                          int lane, int kbase) {
    const int brL = (((lane >> 3) & 1) << 3) + (lane & 7), bcL = (lane >> 4) << 4;
#pragma unroll
    for (int kk = 0; kk < 2; ++kk) {
#pragma unroll
        for (int nt2 = 0; nt2 < 4; ++nt2) {
            u32 bd = bHi + off64(kbase + kk * 16 + brL, (nt2 << 5) + bcL);
            u32 bh0, bh1, bh2, bh3, bl0, bl1, bl2, bl3;
            ldsm4t(bd,      bh0, bh1, bh2, bh3);
            ldsm4t(bd + HL, bl0, bl1, bl2, bl3);
#pragma unroll
            for (int mt = 0; mt < 2; ++mt) {
                float* c0 = po[mt][nt2 * 2];
                float* c1 = po[mt][nt2 * 2 + 1];
                mma_bf16(c0, pH[mt][kk][0], pH[mt][kk][1], pH[mt][kk][2], pH[mt][kk][3], bh0, bh1);
                mma_bf16(c1, pH[mt][kk][0], pH[mt][kk][1], pH[mt][kk][2], pH[mt][kk][3], bh2, bh3);
                mma_bf16(c0, pH[mt][kk][0], pH[mt][kk][1], pH[mt][kk][2], pH[mt][kk][3], bl0, bl1);
                mma_bf16(c1, pH[mt][kk][0], pH[mt][kk][1], pH[mt][kk][2], pH[mt][kk][3], bl2, bl3);
                mma_bf16(c0, pL[mt][kk][0], pL[mt][kk][1], pL[mt][kk][2], pL[mt][kk][3], bh0, bh1);
                mma_bf16(c1, pL[mt][kk][0], pL[mt][kk][1], pL[mt][kk][2], pL[mt][kk][3], bh2, bh3);
            }
        }
    }
}

#define ZERO8(po) \
    _Pragma("unroll") for (int mt = 0; mt < 2; ++mt) \
    _Pragma("unroll") for (int nt = 0; nt < 8; ++nt) \
    _Pragma("unroll") for (int e = 0; e < 4; ++e) (po)[mt][nt][e] = 0.0f;
#define ZERO4(a) \
    _Pragma("unroll") for (int mt = 0; mt < 2; ++mt) \
    _Pragma("unroll") for (int nt = 0; nt < 4; ++nt) \
    _Pragma("unroll") for (int e = 0; e < 4; ++e) (a)[mt][nt][e] = 0.0f;

__global__ void __launch_bounds__(128, 3)
ttt_mma_kernel(const float* __restrict__ qkv, float* __restrict__ out) {
    extern __shared__ char sm[];
    const u32 sb = smem_u32(sm);
    const int tid = threadIdx.x, lane = tid & 31, wid = tid >> 5;
    const int wm = wid & 1, wn = wid >> 1;
    const int mbase = wm * 32, nbase = wn * 32;

    const int mb = (NMB - 1) - (int)blockIdx.y;     // heavy T-blocks first
    const int bh = blockIdx.x, b = bh >> 4, h = bh & 15;
    const float* base = qkv + (size_t)b * S_LEN * ROWSTRIDE + h * DIM;
    const float* gQ = base;
    const float* gK = base + NH * DIM;
    const float* gV = base + 2 * NH * DIM;
    const int t0 = mb * BLKM;
    const int nK = mb + 1;                          // 64-row K blocks needed
    const bool diagDead = (wm == 0 && wn == 1);     // fully-masked diag quadrant
    const int tri = (mb * (mb + 1)) / 2;
    // per-thread A1 scratch base (coalesced)
    float* scr0 = g_s1 + ((size_t)(bh * NTILE + tri) << 12) + (tid << 2);
    // K bf16-image scratch base (16KB per tile)
    char* kscr0 = reinterpret_cast<char*>(g_kc) + ((size_t)(bh * NTILE + tri) << 14);

    // kick K0 -> fp32 stage (V buffer, free in pass 1); Q LDG overlaps the copy
    cpasync64(sb + OFF_V, gK, tid);
    load_split(sm, OFF_Q, gQ + (size_t)t0 * ROWSTRIDE, 2.0f, tid);

    // ================= pass 1: po = partial of tril(2Q K^T) K  (= 2*O2) =================
    float po[2][8][4];
    ZERO8(po);
    for (int j = 0; j < nK; ++j) {
        CP_WAIT0(); __syncthreads();                // stage holds K_j; prev gemm2 done with sK
        convert_stage_store(sm, OFF_V, kscr0 + ((size_t)j << 14), tid);  // K_j -> sK + scratch
        __syncthreads();                            // sK visible; stage free
        if (j + 1 < nK)
            cpasync64(sb + OFF_V, gK + (size_t)(j + 1) * BLKS * ROWSTRIDE, tid);

        if (!(j == nK - 1 && diagDead)) {
            float acc1[2][4][4];
            ZERO4(acc1);
            gemm_nT(sb + OFF_Q, sb + OFF_K, acc1, lane, mbase, nbase);  // 2Q K^T
            // store raw A1' tile to scratch (pre-mask, evict-first) for pass 2
            {
                float* sp = scr0 + ((size_t)j << 12);
                const float* a = &acc1[0][0][0];
#pragma unroll
                for (int i = 0; i < 8; ++i)
                    stg_cs4(sp + i * 512, a[i*4], a[i*4+1], a[i*4+2], a[i*4+3]);
            }
            u32 pH[2][2][4], pL[2][2][4];
            mask_pack(acc1, pH, pL, lane, t0 + mbase, j * BLKS + nbase, j == nK - 1);
            gemm2_reg(pH, pL, sb + OFF_K, po, lane, nbase);             // += S K
        }
    }

    // cross-warp reduce po (wn pairs) -> -O2 split tiles in sO2
    __syncthreads();
    // prologue for pass 2: K0 bf16 image -> OFF_Q (overlaps the reduce below)
    cpasync_lin(sb + OFF_Q, kscr0, tid);
    if (wn == 1) {
#pragma unroll
        for (int mt = 0; mt < 2; ++mt)
#pragma unroll
            for (int nt = 0; nt < 8; ++nt)
#pragma unroll
                for (int rr = 0; rr < 2; ++rr) {
                    int rl = mt * 16 + (lane >> 2) + rr * 8;
                    int col = nt * 8 + ((lane & 3) << 1);
                    float2 v = make_float2(po[mt][nt][rr * 2], po[mt][nt][rr * 2 + 1]);
                    *reinterpret_cast<float2*>(sm + RED_OFF + wm * 8192 + rl * 256 + col * 4) = v;
                }
    }
    __syncthreads();
    if (wn == 0) {
#pragma unroll
        for (int mt = 0; mt < 2; ++mt)
#pragma unroll
            for (int nt = 0; nt < 8; ++nt)
#pragma unroll
                for (int rr = 0; rr < 2; ++rr) {
                    int rl = mt * 16 + (lane >> 2) + rr * 8;
                    int col = nt * 8 + ((lane & 3) << 1);
                    float2 p = *reinterpret_cast<float2*>(sm + RED_OFF + wm * 8192 + rl * 256 + col * 4);
                    float v0 = -0.5f * (po[mt][nt][rr * 2]     + p.x);
                    float v1 = -0.5f * (po[mt][nt][rr * 2 + 1] + p.y);
                    u32 hp, lp;
                    split_pack(v0, v1, hp, lp);
                    u32 o = off64(mbase + rl, col << 1);
                    *reinterpret_cast<u32*>(sm + OFF_O2 + o)      = hp;
                    *reinterpret_cast<u32*>(sm + OFF_O2 + HL + o) = lp;
                }
    }

    // ===== pass 2: po = partial of tril(A1' + (-O2) K^T) V = (2A1 - A2) V =====
    // K tiles arrive as prebuilt bf16 images via cp.async, ping-pong OFF_Q/OFF_K.
    ZERO8(po);
    for (int j = 0; j < nK; ++j) {
        const bool active = !(j == nK - 1 && diagDead);
        const u32 bufK = sb + ((j & 1) ? OFF_K : OFF_Q);
        const u32 bufN = sb + ((j & 1) ? OFF_Q : OFF_K);
        float acc1[2][4][4];
        if (active) {                               // A1 scratch load (issued pre-wait)
            float* sp = scr0 + ((size_t)j << 12);
            float* a = &acc1[0][0][0];
#pragma unroll
            for (int i = 0; i < 8; ++i)
                ldg_cs4(sp + i * 512, a[i*4], a[i*4+1], a[i*4+2], a[i*4+3]);
        }

        CP_WAIT0(); __syncthreads();                // K_j image in bufK; prev gemms done
        if (j + 1 < nK)
            cpasync_lin(bufN, kscr0 + ((size_t)(j + 1) << 14), tid);
        load_split(sm, OFF_V, gV + (size_t)j * BLKS * ROWSTRIDE, 1.0f, tid);
        __syncthreads();                            // sV visible

        if (active) {
            gemm_nT(sb + OFF_O2, bufK, acc1, lane, mbase, nbase);  // += (-O2) K^T

            u32 pH[2][2][4], pL[2][2][4];
            mask_pack(acc1, pH, pL, lane, t0 + mbase, j * BLKS + nbase, j == nK - 1);

            gemm2_reg(pH, pL, sb + OFF_V, po, lane, nbase);        // += S V
        }
    }

    // cross-warp reduce po -> final out
    __syncthreads();
    if (wn == 1) {
#pragma unroll
        for (int mt = 0; mt < 2; ++mt)
#pragma unroll
            for (int nt = 0; nt < 8; ++nt)
#pragma unroll
                for (int rr = 0; rr < 2; ++rr) {
                    int rl = mt * 16 + (lane >> 2) + rr * 8;
                    int col = nt * 8 + ((lane & 3) << 1);
                    float2 v = make_float2(po[mt][nt][rr * 2], po[mt][nt][rr * 2 + 1]);
                    *reinterpret_cast<float2*>(sm + RED_OFF + wm * 8192 + rl * 256 + col * 4) = v;
                }
    }
    __syncthreads();
    if (wn == 0) {
#pragma unroll
        for (int mt = 0; mt < 2; ++mt)
#pragma unroll
            for (int nt = 0; nt < 8; ++nt)
#pragma unroll
                for (int rr = 0; rr < 2; ++rr) {
                    int rl = mt * 16 + (lane >> 2) + rr * 8;
                    int col = nt * 8 + ((lane & 3) << 1);
                    float2 p = *reinterpret_cast<float2*>(sm + RED_OFF + wm * 8192 + rl * 256 + col * 4);
                    float2 v = make_float2(po[mt][nt][rr * 2] + p.x,
                                           po[mt][nt][rr * 2 + 1] + p.y);
                    size_t off = (((size_t)b * S_LEN + t0 + mbase + rl) * NH + h) * DIM + col;
                    *reinterpret_cast<float2*>(out + off) = v;
                }
    }
}

extern "C" void kernel_launch(void* const* d_in, const int* in_sizes, int n_in,
                              void* d_out, int out_size) {
    const float* qkv = (const float*)d_in[0];
    float* out = (float*)d_out;
    cudaFuncSetAttribute(ttt_mma_kernel, cudaFuncAttributeMaxDynamicSharedMemorySize,
                         SMEM_TOTAL);
    dim3 grid(32 /*b*h*/, NMB /*reversed T-blocks*/);
    ttt_mma_kernel<<<grid, 128, SMEM_TOTAL>>>(qkv, out);
}

// round 14
// speedup vs baseline: 1.1749x; 1.1749x over previous
#include <cuda_runtime.h>
#include <cuda_bf16.h>
#include <cstdint>

typedef uint32_t u32;

#define S_LEN 2048
#define NH 16
#define DIM 64
#define BLKM 64          // T rows per CTA
#define BLKS 64          // K/V rows per j-step
#define NMB 32           // S_LEN / BLKM
#define ROWSTRIDE 3072   // 3*NH*DIM floats between consecutive s rows

#define HL 8192          // one [64][64] bf16 half-tile (hi or lo)
// smem slots (16KB each): S0 = Q image (pass1) / -O2 (pass2); S1/S2 = K ping-pong; S3 = V
#define S0 0
#define S1 16384
#define S2 32768
#define S3 49152
#define SMEM_TOTAL 65536               // -> 3 CTAs/SM
#define RED_OFF S1                     // f32 staging for cross-warp reduce

#define NTILE 528                      // sum_{mb} (mb+1)
// A1 tile cache: [bh][tri(mb)+j][4096 floats], fp32, written pass 1 / read pass 2
// by the SAME thread at the SAME addresses. ~277 MB, .cs streamed.
__device__ float g_s1[(size_t)32 * NTILE * 4096];
// Prebuilt split-bf16 swizzled tile images: [tensor 0=2Q,1=K,2=V][bh][tile j][16KB].
// Built once by prep kernel, shared by all CTAs of the same bh (L2-resident, ~48MB).
__device__ char g_img[(size_t)3 * 32 * 32 * 16384];

__device__ __forceinline__ const char* img(int t, int bh, int j) {
    return g_img + ((size_t)((t * 32 + bh) * 32 + j) << 14);
}

// ------------------------------------------------------------------ helpers
__device__ __forceinline__ u32 smem_u32(const void* p) {
    u32 a; asm("{ .reg .u64 t; cvta.to.shared.u64 t, %1; cvt.u32.u64 %0, t; }"
               : "=r"(a) : "l"(p));
    return a;
}
__device__ __forceinline__ u32 off64(int r, int cb) { return (u32)(r * 128 + (cb ^ ((r & 7) << 4))); }

__device__ __forceinline__ void ldsm4(u32 a, u32& r0, u32& r1, u32& r2, u32& r3) {
    asm volatile("ldmatrix.sync.aligned.m8n8.x4.shared.b16 {%0,%1,%2,%3}, [%4];"
        : "=r"(r0), "=r"(r1), "=r"(r2), "=r"(r3) : "r"(a));
}
__device__ __forceinline__ void ldsm4t(u32 a, u32& r0, u32& r1, u32& r2, u32& r3) {
    asm volatile("ldmatrix.sync.aligned.m8n8.x4.trans.shared.b16 {%0,%1,%2,%3}, [%4];"
        : "=r"(r0), "=r"(r1), "=r"(r2), "=r"(r3) : "r"(a));
}
__device__ __forceinline__ void mma_bf16(float* c, u32 a0, u32 a1, u32 a2, u32 a3,
                                         u32 b0, u32 b1) {
    asm volatile("mma.sync.aligned.m16n8k16.row.col.f32.bf16.bf16.f32 "
        "{%0,%1,%2,%3}, {%4,%5,%6,%7}, {%8,%9}, {%0,%1,%2,%3};"
        : "+f"(c[0]), "+f"(c[1]), "+f"(c[2]), "+f"(c[3])
        : "r"(a0), "r"(a1), "r"(a2), "r"(a3), "r"(b0), "r"(b1));
}
// fast truncation split: hi = top16 (PRMT pack), lo = x - hi (rn bf16x2 pack)
__device__ __forceinline__ void split_pack(float v0, float v1, u32& hp, u32& lp) {
    u32 u0 = __float_as_uint(v0), u1 = __float_as_uint(v1);
    asm("prmt.b32 %0, %1, %2, 0x7632;" : "=r"(hp) : "r"(u0), "r"(u1));
    float lo0 = v0 - __uint_as_float(u0 & 0xFFFF0000u);
    float lo1 = v1 - __uint_as_float(u1 & 0xFFFF0000u);
    asm("cvt.rn.satfinite.bf16x2.f32 %0, %1, %2;" : "=r"(lp) : "f"(lo1), "f"(lo0));
}
// streaming (evict-first) A1 scratch access
__device__ __forceinline__ void stg_cs4(float* p, float a, float b, float c, float d) {
    asm volatile("st.global.cs.v4.f32 [%0], {%1,%2,%3,%4};"
        :: "l"(p), "f"(a), "f"(b), "f"(c), "f"(d) : "memory");
}
__device__ __forceinline__ void ldg_cs4(const float* p, float& a, float& b, float& c, float& d) {
    asm volatile("ld.global.cs.v4.f32 {%0,%1,%2,%3}, [%4];"
        : "=f"(a), "=f"(b), "=f"(c), "=f"(d) : "l"(p));
}

#define CP_COMMIT() asm volatile("cp.async.commit_group;" ::: "memory")
#define CP_WAIT0()  asm volatile("cp.async.wait_group 0;" ::: "memory")
#define CP_WAIT1()  asm volatile("cp.async.wait_group 1;" ::: "memory")

// ---- cp.async: 16KB linear image -> smem slot (128 thr, 8x16B each) ----
__device__ __forceinline__ void cpasync_img(u32 dst, const char* src, int tid) {
#pragma unroll
    for (int it = 0; it < 8; ++it) {
        int off = (tid + it * 128) * 16;
        asm volatile("cp.async.cg.shared.global [%0], [%1], 16;"
                     :: "r"(dst + (u32)off), "l"(src + off));
    }
    CP_COMMIT();
}

// ==================== prep kernel: qkv -> split-bf16 swizzled images ====================
__global__ void __launch_bounds__(128)
prep_kernel(const float* __restrict__ qkv) {
    const int bh = blockIdx.x, j = blockIdx.y, t = blockIdx.z;
    const int b = bh >> 4, h = bh & 15;
    const int tid = threadIdx.x;
    const float* src = qkv + (size_t)b * S_LEN * ROWSTRIDE
                     + (size_t)(j * BLKS) * ROWSTRIDE + t * (NH * DIM) + h * DIM;
    char* dst = const_cast<char*>(img(t, bh, j));
    const float scale = (t == 0) ? 2.0f : 1.0f;
#pragma unroll
    for (int it = 0; it < 8; ++it) {
        int f = tid + it * 128;
        int s = f >> 4, dq = (f & 15) << 2;
        float4 v = *reinterpret_cast<const float4*>(src + (size_t)s * ROWSTRIDE + dq);
        u32 hp0, lp0, hp1, lp1;
        split_pack(v.x * scale, v.y * scale, hp0, lp0);
        split_pack(v.z * scale, v.w * scale, hp1, lp1);
        u32 o = off64(s, dq << 1);
        *reinterpret_cast<uint2*>(dst + o)      = make_uint2(hp0, hp1);
        *reinterpret_cast<uint2*>(dst + HL + o) = make_uint2(lp0, lp1);
    }
}

// ---- GEMM1: acc[32x32 slice] += A[64x64] * (B[64x64])^T, 3-term split ----
__device__ __forceinline__ void gemm_nT(u32 aHi, u32 bHi, float (&acc)[2][4][4],
                                        int lane, int mbase, int nbase) {
    const int arL = lane & 15, acL = (lane >> 4) << 4;
    const int brL = ((lane >> 4) << 3) + (lane & 7), bcL = ((lane >> 3) & 1) << 4;
#pragma unroll
    for (int kk = 0; kk < 4; ++kk) {
        const int kb = kk << 5;
        u32 aH[2][4], aL[2][4];
#pragma unroll
        for (int mt = 0; mt < 2; ++mt) {
            u32 ad = aHi + off64(mbase + mt * 16 + arL, kb + acL);
            ldsm4(ad,      aH[mt][0], aH[mt][1], aH[mt][2], aH[mt][3]);
            ldsm4(ad + HL, aL[mt][0], aL[mt][1], aL[mt][2], aL[mt][3]);
        }
#pragma unroll
        for (int nt2 = 0; nt2 < 2; ++nt2) {
            u32 bd = bHi + off64(nbase + nt2 * 16 + brL, kb + bcL);
            u32 bh0, bh1, bh2, bh3, bl0, bl1, bl2, bl3;
            ldsm4(bd,      bh0, bh1, bh2, bh3);
            ldsm4(bd + HL, bl0, bl1, bl2, bl3);
#pragma unroll
            for (int mt = 0; mt < 2; ++mt) {
                float* c0 = acc[mt][nt2 * 2];
                float* c1 = acc[mt][nt2 * 2 + 1];
                mma_bf16(c0, aH[mt][0], aH[mt][1], aH[mt][2], aH[mt][3], bh0, bh1);
                mma_bf16(c1, aH[mt][0], aH[mt][1], aH[mt][2], aH[mt][3], bh2, bh3);
                mma_bf16(c0, aH[mt][0], aH[mt][1], aH[mt][2], aH[mt][3], bl0, bl1);
                mma_bf16(c1, aH[mt][0], aH[mt][1], aH[mt][2], aH[mt][3], bl2, bl3);
                mma_bf16(c0, aL[mt][0], aL[mt][1], aL[mt][2], aL[mt][3], bh0, bh1);
                mma_bf16(c1, aL[mt][0], aL[mt][1], aL[mt][2], aL[mt][3], bh2, bh3);
            }
        }
    }
}

// ---- mask (absolute row/col) + in-register split into A-operand packs ----
__device__ __forceinline__ void mask_pack(float (&acc)[2][4][4],
                                          u32 (&pH)[2][2][4], u32 (&pL)[2][2][4],
                                          int lane, int rowAbs0, int colAbs0, bool diag) {
    if (diag) {
#pragma unroll
        for (int mt = 0; mt < 2; ++mt)
#pragma unroll
            for (int nt = 0; nt < 4; ++nt) {
                int col = colAbs0 + nt * 8 + ((lane & 3) << 1);
#pragma unroll
                for (int rr = 0; rr < 2; ++rr) {
                    int row = rowAbs0 + mt * 16 + (lane >> 2) + rr * 8;
                    if (col     > row) acc[mt][nt][rr * 2 + 0] = 0.0f;
                    if (col + 1 > row) acc[mt][nt][rr * 2 + 1] = 0.0f;
                }
            }
    }
#pragma unroll
    for (int mt = 0; mt < 2; ++mt)
#pragma unroll
        for (int kk = 0; kk < 2; ++kk) {
            split_pack(acc[mt][2*kk  ][0], acc[mt][2*kk  ][1], pH[mt][kk][0], pL[mt][kk][0]);
            split_pack(acc[mt][2*kk  ][2], acc[mt][2*kk  ][3], pH[mt][kk][1], pL[mt][kk][1]);
            split_pack(acc[mt][2*kk+1][0], acc[mt][2*kk+1][1], pH[mt][kk][2], pL[mt][kk][2]);
            split_pack(acc[mt][2*kk+1][2], acc[mt][2*kk+1][3], pH[mt][kk][3], pL[mt][kk][3]);
        }
}

// ---- GEMM2: po[32x64] += S_slice(regs, 32 k) * B[k-slice x 64], B via ldmatrix.trans ----
__device__ __forceinline__ void gemm2_reg(const u32 (&pH)[2][2][4], const u32 (&pL)[2][2][4],
                                          u32 bHi, float (&po)[2][8][4],
                                          int lane, int kbase) {
    const int brL = (((lane >> 3) & 1) << 3) + (lane & 7), bcL = (lane >> 4) << 4;
#pragma unroll
    for (int kk = 0; kk < 2; ++kk) {
#pragma unroll
        for (int nt2 = 0; nt2 < 4; ++nt2) {
            u32 bd = bHi + off64(kbase + kk * 16 + brL, (nt2 << 5) + bcL);
            u32 bh0, bh1, bh2, bh3, bl0, bl1, bl2, bl3;
            ldsm4t(bd,      bh0, bh1, bh2, bh3);
            ldsm4t(bd + HL, bl0, bl1, bl2, bl3);
#pragma unroll
            for (int mt = 0; mt < 2; ++mt) {
                float* c0 = po[mt][nt2 * 2];
                float* c1 = po[mt][nt2 * 2 + 1];
                mma_bf16(c0, pH[mt][kk][0], pH[mt][kk][1], pH[mt][kk][2], pH[mt][kk][3], bh0, bh1);
                mma_bf16(c1, pH[mt][kk][0], pH[mt][kk][1], pH[mt][kk][2], pH[mt][kk][3], bh2, bh3);
                mma_bf16(c0, pH[mt][kk][0], pH[mt][kk][1], pH[mt][kk][2], pH[mt][kk][3], bl0, bl1);
                mma_bf16(c1, pH[mt][kk][0], pH[mt][kk][1], pH[mt][kk][2], pH[mt][kk][3], bl2, bl3);
                mma_bf16(c0, pL[mt][kk][0], pL[mt][kk][1], pL[mt][kk][2], pL[mt][kk][3], bh0, bh1);
                mma_bf16(c1, pL[mt][kk][0], pL[mt][kk][1], pL[mt][kk][2], pL[mt][kk][3], bh2, bh3);
            }
        }
    }
}

#define ZERO8(po) \
    _Pragma("unroll") for (int mt = 0; mt < 2; ++mt) \
    _Pragma("unroll") for (int nt = 0; nt < 8; ++nt) \
    _Pragma("unroll") for (int e = 0; e < 4; ++e) (po)[mt][nt][e] = 0.0f;
#define ZERO4(a) \
    _Pragma("unroll") for (int mt = 0; mt < 2; ++mt) \
    _Pragma("unroll") for (int nt = 0; nt < 4; ++nt) \
    _Pragma("unroll") for (int e = 0; e < 4; ++e) (a)[mt][nt][e] = 0.0f;

__global__ void __launch_bounds__(128, 3)
ttt_mma_kernel(float* __restrict__ out) {
    extern __shared__ char sm[];
    const u32 sb = smem_u32(sm);
    const int tid = threadIdx.x, lane = tid & 31, wid = tid >> 5;
    const int wm = wid & 1, wn = wid >> 1;
    const int mbase = wm * 32, nbase = wn * 32;

    const int mb = (NMB - 1) - (int)blockIdx.y;     // heavy T-blocks first
    const int bh = blockIdx.x, b = bh >> 4, h = bh & 15;
    const int t0 = mb * BLKM;
    const int nK = mb + 1;                          // 64-row K blocks needed
    const bool diagDead = (wm == 0 && wn == 1);     // fully-masked diag quadrant
    const int tri = (mb * (mb + 1)) / 2;
    float* scr0 = g_s1 + ((size_t)(bh * NTILE + tri) << 12) + (tid << 2);

    // prologue: 2Q image -> S0, K_0 image -> S1
    cpasync_img(sb + S0, img(0, bh, mb), tid);
    cpasync_img(sb + S1, img(1, bh, 0), tid);

    // ================= pass 1: po = partial of tril(2Q K^T) K  (= 2*O2) =================
    float po[2][8][4];
    ZERO8(po);
    for (int j = 0; j < nK; ++j) {
        CP_WAIT0(); __syncthreads();                // K_j visible; all warps done with j-1
        const u32 bufK = sb + ((j & 1) ? S2 : S1);
        if (j + 1 < nK)
            cpasync_img(sb + ((j & 1) ? S1 : S2), img(1, bh, j + 1), tid);

        if (!(j == nK - 1 && diagDead)) {
            float acc1[2][4][4];
            ZERO4(acc1);
            gemm_nT(sb + S0, bufK, acc1, lane, mbase, nbase);           // 2Q K^T
            // store raw A1' tile to scratch (pre-mask, evict-first) for pass 2
            {
                float* sp = scr0 + ((size_t)j << 12);
                const float* a = &acc1[0][0][0];
#pragma unroll
                for (int i = 0; i < 8; ++i)
                    stg_cs4(sp + i * 512, a[i*4], a[i*4+1], a[i*4+2], a[i*4+3]);
            }
            u32 pH[2][2][4], pL[2][2][4];
            mask_pack(acc1, pH, pL, lane, t0 + mbase, j * BLKS + nbase, j == nK - 1);
            gemm2_reg(pH, pL, bufK, po, lane, nbase);                   // += S K
        }
    }

    // cross-warp reduce po (wn pairs) -> -O2 split tiles in S0 (Q dead)
    __syncthreads();
    // pass-2 prologue: K_0 -> S2, V_0 -> S3 (one group)
    {
#pragma unroll
        for (int it = 0; it < 8; ++it) {
            int off = (tid + it * 128) * 16;
            asm volatile("cp.async.cg.shared.global [%0], [%1], 16;"
                         :: "r"(sb + S2 + (u32)off), "l"(img(1, bh, 0) + off));
            asm volatile("cp.async.cg.shared.global [%0], [%1], 16;"
                         :: "r"(sb + S3 + (u32)off), "l"(img(2, bh, 0) + off));
        }
        CP_COMMIT();
    }
    if (wn == 1) {
#pragma unroll
        for (int mt = 0; mt < 2; ++mt)
#pragma unroll
            for (int nt = 0; nt < 8; ++nt)
#pragma unroll
                for (int rr = 0; rr < 2; ++rr) {
                    int rl = mt * 16 + (lane >> 2) + rr * 8;
                    int col = nt * 8 + ((lane & 3) << 1);
                    float2 v = make_float2(po[mt][nt][rr * 2], po[mt][nt][rr * 2 + 1]);
                    *reinterpret_cast<float2*>(sm + RED_OFF + wm * 8192 + rl * 256 + col * 4) = v;
                }
    }
    __syncthreads();
    if (wn == 0) {
#pragma unroll
        for (int mt = 0; mt < 2; ++mt)
#pragma unroll
            for (int nt = 0; nt < 8; ++nt)
#pragma unroll
                for (int rr = 0; rr < 2; ++rr) {
                    int rl = mt * 16 + (lane >> 2) + rr * 8;
                    int col = nt * 8 + ((lane & 3) << 1);
                    float2 p = *reinterpret_cast<float2*>(sm + RED_OFF + wm * 8192 + rl * 256 + col * 4);
                    float v0 = -0.5f * (po[mt][nt][rr * 2]     + p.x);
                    float v1 = -0.5f * (po[mt][nt][rr * 2 + 1] + p.y);
                    u32 hp, lp;
                    split_pack(v0, v1, hp, lp);
                    u32 o = off64(mbase + rl, col << 1);
                    *reinterpret_cast<u32*>(sm + S0 + o)      = hp;
                    *reinterpret_cast<u32*>(sm + S0 + HL + o) = lp;
                }
    }

    // ===== pass 2: po = partial of tril(A1' + (-O2) K^T) V = (2A1 - A2) V =====
    // K images ping-pong S2/S1 (prefetch depth 1); V image single-slot S3 (wait_group).
    ZERO8(po);
    for (int j = 0; j < nK; ++j) {
        const bool active = !(j == nK - 1 && diagDead);
        float acc1[2][4][4];
        if (active) {                               // A1 scratch load (overlaps cp.async)
            float* sp = scr0 + ((size_t)j << 12);
            float* a = &acc1[0][0][0];
#pragma unroll
            for (int i = 0; i < 8; ++i)
                ldg_cs4(sp + i * 512, a[i*4], a[i*4+1], a[i*4+2], a[i*4+3]);
        }

        __syncthreads();                            // all warps done with j-1 (S3, old K free)
        if (j > 0)
            cpasync_img(sb + S3, img(2, bh, j), tid);          // V_j
        if (j + 1 < nK) {
            cpasync_img(sb + ((j & 1) ? S2 : S1), img(1, bh, j + 1), tid);  // K_{j+1}
            CP_WAIT1();                             // K_j + V_j done; K_{j+1} in flight
        } else {
            CP_WAIT0();
        }
        __syncthreads();                            // visibility

        if (active) {
            const u32 bufK = sb + ((j & 1) ? S1 : S2);
            gemm_nT(sb + S0, bufK, acc1, lane, mbase, nbase);   // += (-O2) K^T

            u32 pH[2][2][4], pL[2][2][4];
            mask_pack(acc1, pH, pL, lane, t0 + mbase, j * BLKS + nbase, j == nK - 1);

            gemm2_reg(pH, pL, sb + S3, po, lane, nbase);        // += S V
        }
    }

    // cross-warp reduce po -> final out
    __syncthreads();
    if (wn == 1) {
#pragma unroll
        for (int mt = 0; mt < 2; ++mt)
#pragma unroll
            for (int nt = 0; nt < 8; ++nt)
#pragma unroll
                for (int rr = 0; rr < 2; ++rr) {
                    int rl = mt * 16 + (lane >> 2) + rr * 8;
                    int col = nt * 8 + ((lane & 3) << 1);
                    float2 v = make_float2(po[mt][nt][rr * 2], po[mt][nt][rr * 2 + 1]);
                    *reinterpret_cast<float2*>(sm + RED_OFF + wm * 8192 + rl * 256 + col * 4) = v;
                }
    }
    __syncthreads();
    if (wn == 0) {
#pragma unroll
        for (int mt = 0; mt < 2; ++mt)
#pragma unroll
            for (int nt = 0; nt < 8; ++nt)
#pragma unroll
                for (int rr = 0; rr < 2; ++rr) {
                    int rl = mt * 16 + (lane >> 2) + rr * 8;
                    int col = nt * 8 + ((lane & 3) << 1);
                    float2 p = *reinterpret_cast<float2*>(sm + RED_OFF + wm * 8192 + rl * 256 + col * 4);
                    float2 v = make_float2(po[mt][nt][rr * 2] + p.x,
                                           po[mt][nt][rr * 2 + 1] + p.y);
                    size_t off = (((size_t)b * S_LEN + t0 + mbase + rl) * NH + h) * DIM + col;
                    *reinterpret_cast<float2*>(out + off) = v;
                }
    }
}

extern "C" void kernel_launch(void* const* d_in, const int* in_sizes, int n_in,
                              void* d_out, int out_size) {
    const float* qkv = (const float*)d_in[0];
    float* out = (float*)d_out;
    cudaFuncSetAttribute(ttt_mma_kernel, cudaFuncAttributeMaxDynamicSharedMemorySize,
                         SMEM_TOTAL);
    dim3 pgrid(32, 32, 3);
    prep_kernel<<<pgrid, 128>>>(qkv);
    dim3 grid(32 /*b*h*/, NMB /*reversed T-blocks*/);
    ttt_mma_kernel<<<grid, 128, SMEM_TOTAL>>>(out);
}

// round 15
// speedup vs baseline: 1.2115x; 1.0312x over previous
#include <cuda_runtime.h>
#include <cuda_bf16.h>
#include <cstdint>

typedef uint32_t u32;

#define S_LEN 2048
#define NH 16
#define DIM 64
#define BLKM 64          // T rows per CTA
#define BLKS 64          // K/V rows per j-step
#define NMB 32           // S_LEN / BLKM
#define ROWSTRIDE 3072   // 3*NH*DIM floats between consecutive s rows

#define HL 8192          // one [64][64] bf16 half-tile (hi or lo)
// smem slots (16KB each): S0 = Q (pass1) / -O2 (pass2); S1/S2 = K ping-pong; S3 = V
#define S0 0
#define S1 16384
#define S2 32768
#define S3 49152
#define SMEM_TOTAL 65536               // -> 3 CTAs/SM
#define RED_OFF S1                     // f32 staging for cross-warp reduce

#define NTILE 528                      // sum_{mb} (mb+1)
// A1 tile cache: [bh][tri(mb)+j][4096 floats], fp32, written pass 1 / read pass 2
// by the SAME thread at the SAME addresses. ~277 MB, .cs streamed.
__device__ float g_s1[(size_t)32 * NTILE * 4096];
// Prebuilt split-bf16 swizzled tile images: [tensor 1=K,2=V][bh][tile j][16KB].
// Built once by prep kernel, shared by all CTAs of the same bh.
__device__ char g_img[(size_t)3 * 32 * 32 * 16384];

__device__ __forceinline__ const char* img(int t, int bh, int j) {
    return g_img + ((size_t)((t * 32 + bh) * 32 + j) << 14);
}

// ------------------------------------------------------------------ helpers
__device__ __forceinline__ u32 smem_u32(const void* p) {
    u32 a; asm("{ .reg .u64 t; cvta.to.shared.u64 t, %1; cvt.u32.u64 %0, t; }"
               : "=r"(a) : "l"(p));
    return a;
}
__device__ __forceinline__ u32 off64(int r, int cb) { return (u32)(r * 128 + (cb ^ ((r & 7) << 4))); }

__device__ __forceinline__ void ldsm4(u32 a, u32& r0, u32& r1, u32& r2, u32& r3) {
    asm volatile("ldmatrix.sync.aligned.m8n8.x4.shared.b16 {%0,%1,%2,%3}, [%4];"
        : "=r"(r0), "=r"(r1), "=r"(r2), "=r"(r3) : "r"(a));
}
__device__ __forceinline__ void ldsm4t(u32 a, u32& r0, u32& r1, u32& r2, u32& r3) {
    asm volatile("ldmatrix.sync.aligned.m8n8.x4.trans.shared.b16 {%0,%1,%2,%3}, [%4];"
        : "=r"(r0), "=r"(r1), "=r"(r2), "=r"(r3) : "r"(a));
}
__device__ __forceinline__ void mma_bf16(float* c, u32 a0, u32 a1, u32 a2, u32 a3,
                                         u32 b0, u32 b1) {
    asm volatile("mma.sync.aligned.m16n8k16.row.col.f32.bf16.bf16.f32 "
        "{%0,%1,%2,%3}, {%4,%5,%6,%7}, {%8,%9}, {%0,%1,%2,%3};"
        : "+f"(c[0]), "+f"(c[1]), "+f"(c[2]), "+f"(c[3])
        : "r"(a0), "r"(a1), "r"(a2), "r"(a3), "r"(b0), "r"(b1));
}
// fast truncation split: hi = top16 (PRMT pack), lo = x - hi (rn bf16x2 pack)
__device__ __forceinline__ void split_pack(float v0, float v1, u32& hp, u32& lp) {
    u32 u0 = __float_as_uint(v0), u1 = __float_as_uint(v1);
    asm("prmt.b32 %0, %1, %2, 0x7632;" : "=r"(hp) : "r"(u0), "r"(u1));
    float lo0 = v0 - __uint_as_float(u0 & 0xFFFF0000u);
    float lo1 = v1 - __uint_as_float(u1 & 0xFFFF0000u);
    asm("cvt.rn.satfinite.bf16x2.f32 %0, %1, %2;" : "=r"(lp) : "f"(lo1), "f"(lo0));
}
// streaming (evict-first) A1 scratch access
__device__ __forceinline__ void stg_cs4(float* p, float a, float b, float c, float d) {
    asm volatile("st.global.cs.v4.f32 [%0], {%1,%2,%3,%4};"
        :: "l"(p), "f"(a), "f"(b), "f"(c), "f"(d) : "memory");
}
__device__ __forceinline__ void ldg_cs4(const float* p, float& a, float& b, float& c, float& d) {
    asm volatile("ld.global.cs.v4.f32 {%0,%1,%2,%3}, [%4];"
        : "=f"(a), "=f"(b), "=f"(c), "=f"(d) : "l"(p));
}

#define CP_COMMIT() asm volatile("cp.async.commit_group;" ::: "memory")
#define CP_WAIT0()  asm volatile("cp.async.wait_group 0;" ::: "memory")
#define CP_WAIT1()  asm volatile("cp.async.wait_group 1;" ::: "memory")
#define CP_WAIT2()  asm volatile("cp.async.wait_group 2;" ::: "memory")

// ---- cp.async: 16KB linear image -> smem slot (128 thr, 8x16B each) ----
__device__ __forceinline__ void cpasync_img(u32 dst, const char* src, int tid) {
#pragma unroll
    for (int it = 0; it < 8; ++it) {
        int off = (tid + it * 128) * 16;
        asm volatile("cp.async.cg.shared.global [%0], [%1], 16;"
                     :: "r"(dst + (u32)off), "l"(src + off));
    }
    CP_COMMIT();
}

// ---- direct LDG load: 64x64 fp32 -> split-bf16 hi/lo swizzled smem ----
__device__ __forceinline__ void load_split(char* sm, int base, const float* src,
                                           float scale, int tid) {
#pragma unroll
    for (int it = 0; it < 8; ++it) {
        int f = tid + it * 128;
        int s = f >> 4, dq = (f & 15) << 2;
        float4 v = *reinterpret_cast<const float4*>(src + (size_t)s * ROWSTRIDE + dq);
        u32 hp0, lp0, hp1, lp1;
        split_pack(v.x * scale, v.y * scale, hp0, lp0);
        split_pack(v.z * scale, v.w * scale, hp1, lp1);
        u32 o = off64(s, dq << 1);
        *reinterpret_cast<uint2*>(sm + base + o)      = make_uint2(hp0, hp1);
        *reinterpret_cast<uint2*>(sm + base + HL + o) = make_uint2(lp0, lp1);
    }
}

// ==================== prep kernel: K/V -> split-bf16 swizzled images ====================
__global__ void __launch_bounds__(128)
prep_kernel(const float* __restrict__ qkv) {
    const int bh = blockIdx.x, j = blockIdx.y, t = (int)blockIdx.z + 1;  // 1=K, 2=V
    const int b = bh >> 4, h = bh & 15;
    const int tid = threadIdx.x;
    const float* src = qkv + (size_t)b * S_LEN * ROWSTRIDE
                     + (size_t)(j * BLKS) * ROWSTRIDE + t * (NH * DIM) + h * DIM;
    char* dst = const_cast<char*>(img(t, bh, j));
#pragma unroll
    for (int it = 0; it < 8; ++it) {
        int f = tid + it * 128;
        int s = f >> 4, dq = (f & 15) << 2;
        float4 v = *reinterpret_cast<const float4*>(src + (size_t)s * ROWSTRIDE + dq);
        u32 hp0, lp0, hp1, lp1;
        split_pack(v.x, v.y, hp0, lp0);
        split_pack(v.z, v.w, hp1, lp1);
        u32 o = off64(s, dq << 1);
        *reinterpret_cast<uint2*>(dst + o)      = make_uint2(hp0, hp1);
        *reinterpret_cast<uint2*>(dst + HL + o) = make_uint2(lp0, lp1);
    }
}

// ---- GEMM1: acc[32x32 slice] += A[64x64] * (B[64x64])^T, 3-term split ----
__device__ __forceinline__ void gemm_nT(u32 aHi, u32 bHi, float (&acc)[2][4][4],
                                        int lane, int mbase, int nbase) {
    const int arL = lane & 15, acL = (lane >> 4) << 4;
    const int brL = ((lane >> 4) << 3) + (lane & 7), bcL = ((lane >> 3) & 1) << 4;
#pragma unroll
    for (int kk = 0; kk < 4; ++kk) {
        const int kb = kk << 5;
        u32 aH[2][4], aL[2][4];
#pragma unroll
        for (int mt = 0; mt < 2; ++mt) {
            u32 ad = aHi + off64(mbase + mt * 16 + arL, kb + acL);
            ldsm4(ad,      aH[mt][0], aH[mt][1], aH[mt][2], aH[mt][3]);
            ldsm4(ad + HL, aL[mt][0], aL[mt][1], aL[mt][2], aL[mt][3]);
        }
#pragma unroll
        for (int nt2 = 0; nt2 < 2; ++nt2) {
            u32 bd = bHi + off64(nbase + nt2 * 16 + brL, kb + bcL);
            u32 bh0, bh1, bh2, bh3, bl0, bl1, bl2, bl3;
            ldsm4(bd,      bh0, bh1, bh2, bh3);
            ldsm4(bd + HL, bl0, bl1, bl2, bl3);
#pragma unroll
            for (int mt = 0; mt < 2; ++mt) {
                float* c0 = acc[mt][nt2 * 2];
                float* c1 = acc[mt][nt2 * 2 + 1];
                mma_bf16(c0, aH[mt][0], aH[mt][1], aH[mt][2], aH[mt][3], bh0, bh1);
                mma_bf16(c1, aH[mt][0], aH[mt][1], aH[mt][2], aH[mt][3], bh2, bh3);
                mma_bf16(c0, aH[mt][0], aH[mt][1], aH[mt][2], aH[mt][3], bl0, bl1);
                mma_bf16(c1, aH[mt][0], aH[mt][1], aH[mt][2], aH[mt][3], bl2, bl3);
                mma_bf16(c0, aL[mt][0], aL[mt][1], aL[mt][2], aL[mt][3], bh0, bh1);
                mma_bf16(c1, aL[mt][0], aL[mt][1], aL[mt][2], aL[mt][3], bh2, bh3);
            }
        }
    }
}

// ---- mask (absolute row/col) + in-register split into A-operand packs ----
__device__ __forceinline__ void mask_pack(float (&acc)[2][4][4],
                                          u32 (&pH)[2][2][4], u32 (&pL)[2][2][4],
                                          int lane, int rowAbs0, int colAbs0, bool diag) {
    if (diag) {
#pragma unroll
        for (int mt = 0; mt < 2; ++mt)
#pragma unroll
            for (int nt = 0; nt < 4; ++nt) {
                int col = colAbs0 + nt * 8 + ((lane & 3) << 1);
#pragma unroll
                for (int rr = 0; rr < 2; ++rr) {
                    int row = rowAbs0 + mt * 16 + (lane >> 2) + rr * 8;
                    if (col     > row) acc[mt][nt][rr * 2 + 0] = 0.0f;
                    if (col + 1 > row) acc[mt][nt][rr * 2 + 1] = 0.0f;
                }
            }
    }
#pragma unroll
    for (int mt = 0; mt < 2; ++mt)
#pragma unroll
        for (int kk = 0; kk < 2; ++kk) {
            split_pack(acc[mt][2*kk  ][0], acc[mt][2*kk  ][1], pH[mt][kk][0], pL[mt][kk][0]);
            split_pack(acc[mt][2*kk  ][2], acc[mt][2*kk  ][3], pH[mt][kk][1], pL[mt][kk][1]);
            split_pack(acc[mt][2*kk+1][0], acc[mt][2*kk+1][1], pH[mt][kk][2], pL[mt][kk][2]);
            split_pack(acc[mt][2*kk+1][2], acc[mt][2*kk+1][3], pH[mt][kk][3], pL[mt][kk][3]);
        }
}

// ---- GEMM2: po[32x64] += S_slice(regs, 32 k) * B[k-slice x 64], B via ldmatrix.trans ----
__device__ __forceinline__ void gemm2_reg(const u32 (&pH)[2][2][4], const u32 (&pL)[2][2][4],
                                          u32 bHi, float (&po)[2][8][4],
                                          int lane, int kbase) {
    const int brL = (((lane >> 3) & 1) << 3) + (lane & 7), bcL = (lane >> 4) << 4;
#pragma unroll
    for (int kk = 0; kk < 2; ++kk) {
#pragma unroll
        for (int nt2 = 0; nt2 < 4; ++nt2) {
            u32 bd = bHi + off64(kbase + kk * 16 + brL, (nt2 << 5) + bcL);
            u32 bh0, bh1, bh2, bh3, bl0, bl1, bl2, bl3;
            ldsm4t(bd,      bh0, bh1, bh2, bh3);
            ldsm4t(bd + HL, bl0, bl1, bl2, bl3);
#pragma unroll
            for (int mt = 0; mt < 2; ++mt) {
                float* c0 = po[mt][nt2 * 2];
                float* c1 = po[mt][nt2 * 2 + 1];
                mma_bf16(c0, pH[mt][kk][0], pH[mt][kk][1], pH[mt][kk][2], pH[mt][kk][3], bh0, bh1);
                mma_bf16(c1, pH[mt][kk][0], pH[mt][kk][1], pH[mt][kk][2], pH[mt][kk][3], bh2, bh3);
                mma_bf16(c0, pH[mt][kk][0], pH[mt][kk][1], pH[mt][kk][2], pH[mt][kk][3], bl0, bl1);
                mma_bf16(c1, pH[mt][kk][0], pH[mt][kk][1], pH[mt][kk][2], pH[mt][kk][3], bl2, bl3);
                mma_bf16(c0, pL[mt][kk][0], pL[mt][kk][1], pL[mt][kk][2], pL[mt][kk][3], bh0, bh1);
                mma_bf16(c1, pL[mt][kk][0], pL[mt][kk][1], pL[mt][kk][2], pL[mt][kk][3], bh2, bh3);
            }
        }
    }
}

#define ZERO8(po) \
    _Pragma("unroll") for (int mt = 0; mt < 2; ++mt) \
    _Pragma("unroll") for (int nt = 0; nt < 8; ++nt) \
    _Pragma("unroll") for (int e = 0; e < 4; ++e) (po)[mt][nt][e] = 0.0f;
#define ZERO4(a) \
    _Pragma("unroll") for (int mt = 0; mt < 2; ++mt) \
    _Pragma("unroll") for (int nt = 0; nt < 4; ++nt) \
    _Pragma("unroll") for (int e = 0; e < 4; ++e) (a)[mt][nt][e] = 0.0f;

__global__ void __launch_bounds__(128, 3)
ttt_mma_kernel(const float* __restrict__ qkv, float* __restrict__ out) {
    extern __shared__ char sm[];
    const u32 sb = smem_u32(sm);
    const int tid = threadIdx.x, lane = tid & 31, wid = tid >> 5;
    const int wm = wid & 1, wn = wid >> 1;
    const int mbase = wm * 32, nbase = wn * 32;

    const int mb = (NMB - 1) - (int)blockIdx.y;     // heavy T-blocks first
    const int bh = blockIdx.x, b = bh >> 4, h = bh & 15;
    const int t0 = mb * BLKM;
    const int nK = mb + 1;                          // 64-row K blocks needed
    const bool diagDead = (wm == 0 && wn == 1);     // fully-masked diag quadrant
    const int tri = (mb * (mb + 1)) / 2;
    float* scr0 = g_s1 + ((size_t)(bh * NTILE + tri) << 12) + (tid << 2);
    const float* gQ = qkv + (size_t)b * S_LEN * ROWSTRIDE + h * DIM;

    // prologue: K_0 image -> S1 (async), then Q direct convert -> S0 (overlaps)
    cpasync_img(sb + S1, img(1, bh, 0), tid);
    load_split(sm, S0, gQ + (size_t)t0 * ROWSTRIDE, 2.0f, tid);

    // ================= pass 1: po = partial of tril(2Q K^T) K  (= 2*O2) =================
    float po[2][8][4];
    ZERO8(po);
    for (int j = 0; j < nK; ++j) {
        CP_WAIT0(); __syncthreads();                // K_j visible; all warps done with j-1
        const u32 bufK = sb + ((j & 1) ? S2 : S1);
        if (j + 1 < nK)
            cpasync_img(sb + ((j & 1) ? S1 : S2), img(1, bh, j + 1), tid);

        if (!(j == nK - 1 && diagDead)) {
            float acc1[2][4][4];
            ZERO4(acc1);
            gemm_nT(sb + S0, bufK, acc1, lane, mbase, nbase);           // 2Q K^T
            // store raw A1' tile to scratch (pre-mask, evict-first) for pass 2
            {
                float* sp = scr0 + ((size_t)j << 12);
                const float* a = &acc1[0][0][0];
#pragma unroll
                for (int i = 0; i < 8; ++i)
                    stg_cs4(sp + i * 512, a[i*4], a[i*4+1], a[i*4+2], a[i*4+3]);
            }
            u32 pH[2][2][4], pL[2][2][4];
            mask_pack(acc1, pH, pL, lane, t0 + mbase, j * BLKS + nbase, j == nK - 1);
            gemm2_reg(pH, pL, bufK, po, lane, nbase);                   // += S K
        }
    }

    // cross-warp reduce po (wn pairs) -> -O2 split tiles in S0 (Q dead)
    __syncthreads();
    // pass-2 prologue: K_0 -> S2 (own group), V_0 -> S3 (own group); overlaps reduce
    cpasync_img(sb + S2, img(1, bh, 0), tid);
    cpasync_img(sb + S3, img(2, bh, 0), tid);
    if (wn == 1) {
#pragma unroll
        for (int mt = 0; mt < 2; ++mt)
#pragma unroll
            for (int nt = 0; nt < 8; ++nt)
#pragma unroll
                for (int rr = 0; rr < 2; ++rr) {
                    int rl = mt * 16 + (lane >> 2) + rr * 8;
                    int col = nt * 8 + ((lane & 3) << 1);
                    float2 v = make_float2(po[mt][nt][rr * 2], po[mt][nt][rr * 2 + 1]);
                    *reinterpret_cast<float2*>(sm + RED_OFF + wm * 8192 + rl * 256 + col * 4) = v;
                }
    }
    __syncthreads();
    if (wn == 0) {
#pragma unroll
        for (int mt = 0; mt < 2; ++mt)
#pragma unroll
            for (int nt = 0; nt < 8; ++nt)
#pragma unroll
                for (int rr = 0; rr < 2; ++rr) {
                    int rl = mt * 16 + (lane >> 2) + rr * 8;
                    int col = nt * 8 + ((lane & 3) << 1);
                    float2 p = *reinterpret_cast<float2*>(sm + RED_OFF + wm * 8192 + rl * 256 + col * 4);
                    float v0 = -0.5f * (po[mt][nt][rr * 2]     + p.x);
                    float v1 = -0.5f * (po[mt][nt][rr * 2 + 1] + p.y);
                    u32 hp, lp;
                    split_pack(v0, v1, hp, lp);
                    u32 o = off64(mbase + rl, col << 1);
                    *reinterpret_cast<u32*>(sm + S0 + o)      = hp;
                    *reinterpret_cast<u32*>(sm + S0 + HL + o) = lp;
                }
    }

    // ===== pass 2: po = partial of tril(A1' + (-O2) K^T) V = (2A1 - A2) V =====
    // K images ping-pong S2/S1; V single-slot S3 with DEFERRED wait (hidden under gemm_nT).
    ZERO8(po);
    for (int j = 0; j < nK; ++j) {
        const bool active = !(j == nK - 1 && diagDead);
        float acc1[2][4][4];
        if (active) {                               // A1 scratch load (overlaps cp.async)
            float* sp = scr0 + ((size_t)j << 12);
            float* a = &acc1[0][0][0];
#pragma unroll
            for (int i = 0; i < 8; ++i)
                ldg_cs4(sp + i * 512, a[i*4], a[i*4+1], a[i*4+2], a[i*4+3]);
        }

        __syncthreads();                            // all warps done with j-1 slots
        if (j > 0)
            cpasync_img(sb + S3, img(2, bh, j), tid);                   // V_j (own group)
        const bool haveNext = (j + 1 < nK);
        if (haveNext)
            cpasync_img(sb + ((j & 1) ? S2 : S1), img(1, bh, j + 1), tid);  // K_{j+1}
        // wait only for K_j (outstanding after it: V_j, K_{j+1}?)
        if (haveNext) { CP_WAIT2(); } else { CP_WAIT1(); }
        __syncthreads();                            // K_j visible

        if (active) {
            const u32 bufK = sb + ((j & 1) ? S1 : S2);
            gemm_nT(sb + S0, bufK, acc1, lane, mbase, nbase);   // += (-O2) K^T
        }

        // now wait for V_j (its copy ran under gemm_nT)
        if (haveNext) { CP_WAIT1(); } else { CP_WAIT0(); }
        __syncthreads();                            // V_j visible

        if (active) {
            u32 pH[2][2][4], pL[2][2][4];
            mask_pack(acc1, pH, pL, lane, t0 + mbase, j * BLKS + nbase, j == nK - 1);
            gemm2_reg(pH, pL, sb + S3, po, lane, nbase);        // += S V
        }
    }

    // cross-warp reduce po -> final out
    __syncthreads();
    if (wn == 1) {
#pragma unroll
        for (int mt = 0; mt < 2; ++mt)
#pragma unroll
            for (int nt = 0; nt < 8; ++nt)
#pragma unroll
                for (int rr = 0; rr < 2; ++rr) {
                    int rl = mt * 16 + (lane >> 2) + rr * 8;
                    int col = nt * 8 + ((lane & 3) << 1);
                    float2 v = make_float2(po[mt][nt][rr * 2], po[mt][nt][rr * 2 + 1]);
                    *reinterpret_cast<float2*>(sm + RED_OFF + wm * 8192 + rl * 256 + col * 4) = v;
                }
    }
    __syncthreads();
    if (wn == 0) {
#pragma unroll
        for (int mt = 0; mt < 2; ++mt)
#pragma unroll
            for (int nt = 0; nt < 8; ++nt)
#pragma unroll
                for (int rr = 0; rr < 2; ++rr) {
                    int rl = mt * 16 + (lane >> 2) + rr * 8;
                    int col = nt * 8 + ((lane & 3) << 1);
                    float2 p = *reinterpret_cast<float2*>(sm + RED_OFF + wm * 8192 + rl * 256 + col * 4);
                    float2 v = make_float2(po[mt][nt][rr * 2] + p.x,
                                           po[mt][nt][rr * 2 + 1] + p.y);
                    size_t off = (((size_t)b * S_LEN + t0 + mbase + rl) * NH + h) * DIM + col;
                    *reinterpret_cast<float2*>(out + off) = v;
                }
    }
}

extern "C" void kernel_launch(void* const* d_in, const int* in_sizes, int n_in,
                              void* d_out, int out_size) {
    const float* qkv = (const float*)d_in[0];
    float* out = (float*)d_out;
    cudaFuncSetAttribute(ttt_mma_kernel, cudaFuncAttributeMaxDynamicSharedMemorySize,
                         SMEM_TOTAL);
    dim3 pgrid(32, 32, 2);               // K and V images only
    prep_kernel<<<pgrid, 128>>>(qkv);
    dim3 grid(32 /*b*h*/, NMB /*reversed T-blocks*/);
    ttt_mma_kernel<<<grid, 128, SMEM_TOTAL>>>(qkv, out);
}